// round 1
// baseline (speedup 1.0000x reference)
#include <cuda_runtime.h>
#include <cuda_bf16.h>
#include <math.h>

// Problem constants
#define BATCH 2
#define SLEN  2048
#define DMODEL 1024
#define NHEAD 16
#define DH    64
#define DFF   2048
#define ROWS_B0   (SLEN)            // attention path rows (batch 0 only)
#define ROWS_ALL  (BATCH*SLEN)      // 4096

// ---------------- scratch (static device globals; no allocs) ----------------
__device__ float g_q   [SLEN*DMODEL];
__device__ float g_k   [SLEN*DMODEL];
__device__ float g_v   [SLEN*DMODEL];
__device__ float g_ctx [SLEN*DMODEL];
__device__ float g_attn[SLEN*DMODEL];
__device__ float g_x   [ROWS_ALL*DMODEL];
__device__ float g_ffn1[ROWS_ALL*DFF];
__device__ float g_ffn2[ROWS_ALL*DMODEL];

// ---------------- SGEMM: C[M,N] = A[M,K] @ B[K,N] + bias, optional GELU -----
// 128x128 block tile, 16 K-tile, 256 threads, 8x8 per-thread register tile.
__global__ void __launch_bounds__(256) gemm_bias_kernel(
    const float* __restrict__ A, const float* __restrict__ B,
    const float* __restrict__ bias, float* __restrict__ C,
    int M, int N, int K, int gelu)
{
    __shared__ float As[16][128];   // transposed: As[k][m]
    __shared__ float Bs[16][128];   // Bs[k][n]

    const int tid  = threadIdx.x;
    const int row0 = blockIdx.y * 128;
    const int col0 = blockIdx.x * 128;
    const int tx = tid & 15;        // 0..15 -> 8 cols each
    const int ty = tid >> 4;        // 0..15 -> 8 rows each

    const int a_m = tid >> 2;        // 0..63
    const int a_k = (tid & 3) << 2;  // 0,4,8,12
    const int b_k = tid >> 5;        // 0..7
    const int b_n = (tid & 31) << 2; // 0..124

    float acc[8][8];
    #pragma unroll
    for (int i = 0; i < 8; ++i)
        #pragma unroll
        for (int j = 0; j < 8; ++j) acc[i][j] = 0.f;

    for (int kt = 0; kt < K; kt += 16) {
        #pragma unroll
        for (int it = 0; it < 2; ++it) {
            int m = a_m + it*64;
            float4 v = *(const float4*)(A + (size_t)(row0+m)*K + kt + a_k);
            As[a_k+0][m] = v.x; As[a_k+1][m] = v.y;
            As[a_k+2][m] = v.z; As[a_k+3][m] = v.w;
        }
        #pragma unroll
        for (int it = 0; it < 2; ++it) {
            int kk = b_k + it*8;
            *(float4*)(&Bs[kk][b_n]) =
                *(const float4*)(B + (size_t)(kt+kk)*N + col0 + b_n);
        }
        __syncthreads();

        #pragma unroll
        for (int k = 0; k < 16; ++k) {
            float a[8], b[8];
            *(float4*)&a[0] = *(float4*)&As[k][ty*8];
            *(float4*)&a[4] = *(float4*)&As[k][ty*8+4];
            *(float4*)&b[0] = *(float4*)&Bs[k][tx*8];
            *(float4*)&b[4] = *(float4*)&Bs[k][tx*8+4];
            #pragma unroll
            for (int i = 0; i < 8; ++i)
                #pragma unroll
                for (int j = 0; j < 8; ++j)
                    acc[i][j] = fmaf(a[i], b[j], acc[i][j]);
        }
        __syncthreads();
    }

    #pragma unroll
    for (int i = 0; i < 8; ++i) {
        int r = row0 + ty*8 + i;
        #pragma unroll
        for (int j = 0; j < 8; j += 4) {
            int c = col0 + tx*8 + j;
            float4 o;
            float* op = &o.x;
            #pragma unroll
            for (int jj = 0; jj < 4; ++jj) {
                float v = acc[i][j+jj] + bias[c+jj];
                if (gelu) v = 0.5f * v * (1.f + erff(v * 0.70710678118654752f));
                op[jj] = v;
            }
            *(float4*)(C + (size_t)r*N + c) = o;
        }
    }
}

// ---------------- Flash attention (batch 0 only) ----------------------------
// grid: (SLEN/64, NHEAD), block 256. Q/K/V layout: [S, H*dh] = [s*1024 + h*64 + d]
__global__ void __launch_bounds__(256) flash_attn_kernel(
    const float* __restrict__ Q, const float* __restrict__ K,
    const float* __restrict__ V, float* __restrict__ O)
{
    const int h  = blockIdx.y;
    const int q0 = blockIdx.x * 64;

    __shared__ float Qs[64][68];
    __shared__ float Ks[32][68];
    __shared__ float Vs[32][68];
    __shared__ float Ps[64][36];
    __shared__ float m_s[64], l_s[64], corr_s[64];

    const int tid = threadIdx.x;
    const int ti  = tid & 15;    // q-row group: rows ti*4..ti*4+3
    const int tj  = tid >> 4;    // col group

    // load Q tile (64x64)
    for (int e = tid; e < 1024; e += 256) {
        int r = e >> 4, d4 = (e & 15) << 2;
        *(float4*)&Qs[r][d4] =
            *(const float4*)(Q + (size_t)(q0+r)*DMODEL + h*DH + d4);
    }
    if (tid < 64) { m_s[tid] = -1e30f; l_s[tid] = 0.f; }

    float o[4][4];
    #pragma unroll
    for (int i = 0; i < 4; ++i)
        #pragma unroll
        for (int j = 0; j < 4; ++j) o[i][j] = 0.f;

    for (int kt = 0; kt < SLEN; kt += 32) {
        __syncthreads();
        // load K,V tiles (32x64 each)
        for (int e = tid; e < 512; e += 256) {
            int r = e >> 4, d4 = (e & 15) << 2;
            *(float4*)&Ks[r][d4] =
                *(const float4*)(K + (size_t)(kt+r)*DMODEL + h*DH + d4);
            *(float4*)&Vs[r][d4] =
                *(const float4*)(V + (size_t)(kt+r)*DMODEL + h*DH + d4);
        }
        __syncthreads();

        // S = scale * Q K^T : thread computes rows ti*4.., cols tj*2..
        float s[4][2] = {{0.f,0.f},{0.f,0.f},{0.f,0.f},{0.f,0.f}};
        #pragma unroll
        for (int d4 = 0; d4 < DH; d4 += 4) {
            float4 k0 = *(float4*)&Ks[tj*2+0][d4];
            float4 k1 = *(float4*)&Ks[tj*2+1][d4];
            #pragma unroll
            for (int i = 0; i < 4; ++i) {
                float4 q = *(float4*)&Qs[ti*4+i][d4];
                s[i][0] += q.x*k0.x + q.y*k0.y + q.z*k0.z + q.w*k0.w;
                s[i][1] += q.x*k1.x + q.y*k1.y + q.z*k1.z + q.w*k1.w;
            }
        }
        #pragma unroll
        for (int i = 0; i < 4; ++i) {
            Ps[ti*4+i][tj*2+0] = s[i][0]*0.125f;
            Ps[ti*4+i][tj*2+1] = s[i][1]*0.125f;
        }
        __syncthreads();

        // online softmax row update (one thread per row)
        if (tid < 64) {
            float m_old = m_s[tid];
            float mx = m_old;
            #pragma unroll
            for (int c = 0; c < 32; ++c) mx = fmaxf(mx, Ps[tid][c]);
            float corr = expf(m_old - mx);
            float sum = 0.f;
            #pragma unroll
            for (int c = 0; c < 32; ++c) {
                float p = expf(Ps[tid][c] - mx);
                Ps[tid][c] = p;
                sum += p;
            }
            m_s[tid] = mx;
            l_s[tid] = l_s[tid]*corr + sum;
            corr_s[tid] = corr;
        }
        __syncthreads();

        // O = O*corr + P @ V : thread owns rows ti*4.., d-cols tj*4..
        #pragma unroll
        for (int i = 0; i < 4; ++i) {
            float cf = corr_s[ti*4+i];
            #pragma unroll
            for (int j = 0; j < 4; ++j) o[i][j] *= cf;
        }
        #pragma unroll 4
        for (int c = 0; c < 32; ++c) {
            float4 vv = *(float4*)&Vs[c][tj*4];
            #pragma unroll
            for (int i = 0; i < 4; ++i) {
                float p = Ps[ti*4+i][c];
                o[i][0] = fmaf(p, vv.x, o[i][0]);
                o[i][1] = fmaf(p, vv.y, o[i][1]);
                o[i][2] = fmaf(p, vv.z, o[i][2]);
                o[i][3] = fmaf(p, vv.w, o[i][3]);
            }
        }
    }
    __syncthreads();

    #pragma unroll
    for (int i = 0; i < 4; ++i) {
        float inv = 1.f / l_s[ti*4+i];
        float4 res = make_float4(o[i][0]*inv, o[i][1]*inv, o[i][2]*inv, o[i][3]*inv);
        *(float4*)(O + (size_t)(q0+ti*4+i)*DMODEL + h*DH + tj*4) = res;
    }
}

// ---------------- fused residual-add + LayerNorm ----------------------------
// one block (256 thr) per row of 1024. Y row index = row % ymod (broadcast).
__global__ void __launch_bounds__(256) add_ln_kernel(
    const float* __restrict__ X, const float* __restrict__ Y,
    const float* __restrict__ g, const float* __restrict__ b,
    float* __restrict__ out, int ymod)
{
    const int row = blockIdx.x;
    const int tid = threadIdx.x;
    const float* xr = X + (size_t)row*DMODEL;
    const float* yr = Y + (size_t)(row % ymod)*DMODEL;

    float4 xv = *(const float4*)(xr + tid*4);
    float4 yv = *(const float4*)(yr + tid*4);
    float v0 = xv.x + yv.x, v1 = xv.y + yv.y, v2 = xv.z + yv.z, v3 = xv.w + yv.w;

    float sum = v0+v1+v2+v3;
    float sq  = v0*v0 + v1*v1 + v2*v2 + v3*v3;
    #pragma unroll
    for (int off = 16; off; off >>= 1) {
        sum += __shfl_xor_sync(0xffffffffu, sum, off);
        sq  += __shfl_xor_sync(0xffffffffu, sq,  off);
    }
    __shared__ float ssum[8], ssq[8];
    int w = tid >> 5, lane = tid & 31;
    if (lane == 0) { ssum[w] = sum; ssq[w] = sq; }
    __syncthreads();
    if (tid == 0) {
        float ts = 0.f, tq = 0.f;
        #pragma unroll
        for (int i = 0; i < 8; ++i) { ts += ssum[i]; tq += ssq[i]; }
        ssum[0] = ts; ssq[0] = tq;
    }
    __syncthreads();
    const float mu  = ssum[0] * (1.f/DMODEL);
    const float var = ssq[0] * (1.f/DMODEL) - mu*mu;
    const float rstd = rsqrtf(var + 1e-5f);

    int c = tid*4;
    float4 gv = *(const float4*)(g + c);
    float4 bv = *(const float4*)(b + c);
    float4 o;
    o.x = (v0 - mu)*rstd*gv.x + bv.x;
    o.y = (v1 - mu)*rstd*gv.y + bv.y;
    o.z = (v2 - mu)*rstd*gv.z + bv.z;
    o.w = (v3 - mu)*rstd*gv.w + bv.w;
    *(float4*)(out + (size_t)row*DMODEL + c) = o;
}

// ---------------- launch --------------------------------------------------
extern "C" void kernel_launch(void* const* d_in, const int* in_sizes, int n_in,
                              void* d_out, int out_size)
{
    const float* src    = (const float*)d_in[0];
    const float* w_q    = (const float*)d_in[1];
    const float* b_q    = (const float*)d_in[2];
    const float* w_k    = (const float*)d_in[3];
    const float* b_k    = (const float*)d_in[4];
    const float* w_v    = (const float*)d_in[5];
    const float* b_v    = (const float*)d_in[6];
    const float* w_out  = (const float*)d_in[7];
    const float* b_out  = (const float*)d_in[8];
    const float* ln1_g  = (const float*)d_in[9];
    const float* ln1_b  = (const float*)d_in[10];
    const float* ln2_g  = (const float*)d_in[11];
    const float* ln2_b  = (const float*)d_in[12];
    const float* ffn_w1 = (const float*)d_in[13];
    const float* ffn_b1 = (const float*)d_in[14];
    const float* ffn_w2 = (const float*)d_in[15];
    const float* ffn_b2 = (const float*)d_in[16];
    float* out = (float*)d_out;

    float *pq, *pk, *pv, *pctx, *pattn, *px, *pf1, *pf2;
    cudaGetSymbolAddress((void**)&pq,    g_q);
    cudaGetSymbolAddress((void**)&pk,    g_k);
    cudaGetSymbolAddress((void**)&pv,    g_v);
    cudaGetSymbolAddress((void**)&pctx,  g_ctx);
    cudaGetSymbolAddress((void**)&pattn, g_attn);
    cudaGetSymbolAddress((void**)&px,    g_x);
    cudaGetSymbolAddress((void**)&pf1,   g_ffn1);
    cudaGetSymbolAddress((void**)&pf2,   g_ffn2);

    dim3 blk(256);

    // QKV projections (batch 0 only: first SLEN rows of src)
    dim3 g_qkv(DMODEL/128, ROWS_B0/128);       // (8,16)
    gemm_bias_kernel<<<g_qkv, blk>>>(src, w_q, b_q, pq, ROWS_B0, DMODEL, DMODEL, 0);
    gemm_bias_kernel<<<g_qkv, blk>>>(src, w_k, b_k, pk, ROWS_B0, DMODEL, DMODEL, 0);
    gemm_bias_kernel<<<g_qkv, blk>>>(src, w_v, b_v, pv, ROWS_B0, DMODEL, DMODEL, 0);

    // attention (batch 0)
    dim3 g_att(SLEN/64, NHEAD);                // (32,16)
    flash_attn_kernel<<<g_att, blk>>>(pq, pk, pv, pctx);

    // output projection
    gemm_bias_kernel<<<g_qkv, blk>>>(pctx, w_out, b_out, pattn, ROWS_B0, DMODEL, DMODEL, 0);

    // x = LN1(src + attn_out[0] broadcast)
    add_ln_kernel<<<ROWS_ALL, blk>>>(src, pattn, ln1_g, ln1_b, px, SLEN);

    // FFN
    dim3 g_f1(DFF/128,    ROWS_ALL/128);       // (16,32)
    dim3 g_f2(DMODEL/128, ROWS_ALL/128);       // (8,32)
    gemm_bias_kernel<<<g_f1, blk>>>(px,  ffn_w1, ffn_b1, pf1, ROWS_ALL, DFF,    DMODEL, 1);
    gemm_bias_kernel<<<g_f2, blk>>>(pf1, ffn_w2, ffn_b2, pf2, ROWS_ALL, DMODEL, DFF,    0);

    // out = LN2(x + ffn)
    add_ln_kernel<<<ROWS_ALL, blk>>>(px, pf2, ln2_g, ln2_b, out, ROWS_ALL);
}

// round 3
// speedup vs baseline: 4.7493x; 4.7493x over previous
#include <cuda_runtime.h>
#include <cuda_bf16.h>
#include <math.h>

// Problem constants
#define BATCH 2
#define SLEN  2048
#define DMODEL 1024
#define NHEAD 16
#define DH    64
#define DFF   2048
#define ROWS_B0   (SLEN)
#define ROWS_ALL  (BATCH*SLEN)

// ---------------- scratch (static device globals; no allocs) ----------------
__device__ float g_q   [SLEN*DMODEL];
__device__ float g_k   [SLEN*DMODEL];
__device__ float g_v   [SLEN*DMODEL];
__device__ float g_ctx [SLEN*DMODEL];
__device__ float g_attn[SLEN*DMODEL];
__device__ float g_x   [ROWS_ALL*DMODEL];
__device__ float g_ffn1[ROWS_ALL*DFF];
__device__ float g_ffn2[ROWS_ALL*DMODEL];

// ---------------- tf32 helpers ----------------------------------------------
__device__ __forceinline__ unsigned f2tf(float x) {
    unsigned r;
    asm("cvt.rna.tf32.f32 %0, %1;" : "=r"(r) : "f"(x));
    return r;
}
__device__ __forceinline__ void st4tf(float* dst, float4 v) {
    float4 o;
    o.x = __uint_as_float(f2tf(v.x));
    o.y = __uint_as_float(f2tf(v.y));
    o.z = __uint_as_float(f2tf(v.z));
    o.w = __uint_as_float(f2tf(v.w));
    *(float4*)dst = o;
}
// D += A(16x8) * B(8x8), tf32 inputs, fp32 accumulate
__device__ __forceinline__ void mma_tf32(float c[4], const unsigned a[4],
                                         unsigned b0, unsigned b1) {
    asm volatile(
        "mma.sync.aligned.m16n8k8.row.col.f32.tf32.tf32.f32 "
        "{%0,%1,%2,%3},{%4,%5,%6,%7},{%8,%9},{%0,%1,%2,%3};"
        : "+f"(c[0]), "+f"(c[1]), "+f"(c[2]), "+f"(c[3])
        : "r"(a[0]), "r"(a[1]), "r"(a[2]), "r"(a[3]), "r"(b0), "r"(b1));
}

// ---------------- tf32 tensor-core GEMM -------------------------------------
// C[M,N] = A[M,K] @ B[K,N] + bias (+ optional exact GELU)
// 128x128 block tile, K-tile 32, 256 threads = 8 warps (4 Mwarps x 2 Nwarps),
// warp tile 32x64 via m16n8k8: 2 Mtiles x 8 Ntiles.
#define AS_STRIDE 36
#define BS_STRIDE 136
__global__ void __launch_bounds__(256) gemm_tf32_kernel(
    const float* __restrict__ A, const float* __restrict__ B,
    const float* __restrict__ bias, float* __restrict__ C,
    int M, int N, int K, int gelu)
{
    __shared__ float As[128 * AS_STRIDE];   // [m][k], pad for conflict-free frags
    __shared__ float Bs[32 * BS_STRIDE];    // [k][n], pad 136 -> bank 8c+g

    const int tid  = threadIdx.x;
    const int lane = tid & 31;
    const int warp = tid >> 5;
    const int g = lane >> 2, c = lane & 3;
    const int wm = warp >> 1, wn = warp & 1;
    const int row0 = blockIdx.y * 128;
    const int col0 = blockIdx.x * 128;

    float acc[2][8][4];
    #pragma unroll
    for (int mt = 0; mt < 2; ++mt)
        #pragma unroll
        for (int nt = 0; nt < 8; ++nt)
            #pragma unroll
            for (int i = 0; i < 4; ++i) acc[mt][nt][i] = 0.f;

    // gmem load assignments (4 float4 each for A and B per thread per stage)
    float4 aReg[4], bReg[4];
    const int nstages = K / 32;

    // prologue load: stage 0
    #pragma unroll
    for (int i = 0; i < 4; ++i) {
        int aidx = tid + i * 256;                  // over 1024 float4
        int ar = aidx >> 3, ac = (aidx & 7) << 2;  // 128 rows x 8 f4
        aReg[i] = *(const float4*)(A + (size_t)(row0 + ar) * K + ac);
        int br = aidx >> 5, bc = (aidx & 31) << 2; // 32 rows x 32 f4
        bReg[i] = *(const float4*)(B + (size_t)br * N + col0 + bc);
    }

    for (int s = 0; s < nstages; ++s) {
        // commit staged regs to smem (tf32-converted)
        #pragma unroll
        for (int i = 0; i < 4; ++i) {
            int aidx = tid + i * 256;
            int ar = aidx >> 3, ac = (aidx & 7) << 2;
            st4tf(&As[ar * AS_STRIDE + ac], aReg[i]);
            int br = aidx >> 5, bc = (aidx & 31) << 2;
            st4tf(&Bs[br * BS_STRIDE + bc], bReg[i]);
        }
        __syncthreads();

        if (s + 1 < nstages) {
            int koff = (s + 1) * 32;
            #pragma unroll
            for (int i = 0; i < 4; ++i) {
                int aidx = tid + i * 256;
                int ar = aidx >> 3, ac = (aidx & 7) << 2;
                aReg[i] = *(const float4*)(A + (size_t)(row0 + ar) * K + koff + ac);
                int br = aidx >> 5, bc = (aidx & 31) << 2;
                bReg[i] = *(const float4*)(B + (size_t)(koff + br) * N + col0 + bc);
            }
        }

        #pragma unroll
        for (int kt = 0; kt < 4; ++kt) {
            unsigned a[2][4];
            #pragma unroll
            for (int mt = 0; mt < 2; ++mt) {
                const float* p = &As[(wm * 32 + mt * 16 + g) * AS_STRIDE + kt * 8 + c];
                a[mt][0] = __float_as_uint(p[0]);
                a[mt][1] = __float_as_uint(p[8 * AS_STRIDE]);
                a[mt][2] = __float_as_uint(p[4]);
                a[mt][3] = __float_as_uint(p[8 * AS_STRIDE + 4]);
            }
            #pragma unroll
            for (int nt = 0; nt < 8; ++nt) {
                int ncol = wn * 64 + nt * 8 + g;
                unsigned b0 = __float_as_uint(Bs[(kt * 8 + c) * BS_STRIDE + ncol]);
                unsigned b1 = __float_as_uint(Bs[(kt * 8 + c + 4) * BS_STRIDE + ncol]);
                mma_tf32(acc[0][nt], a[0], b0, b1);
                mma_tf32(acc[1][nt], a[1], b0, b1);
            }
        }
        __syncthreads();
    }

    // epilogue: bias (+gelu), write float2 per fragment half
    #pragma unroll
    for (int mt = 0; mt < 2; ++mt) {
        int r = row0 + wm * 32 + mt * 16 + g;
        #pragma unroll
        for (int nt = 0; nt < 8; ++nt) {
            int cc = col0 + wn * 64 + nt * 8 + 2 * c;
            float bz0 = bias[cc], bz1 = bias[cc + 1];
            float v0 = acc[mt][nt][0] + bz0;
            float v1 = acc[mt][nt][1] + bz1;
            float v2 = acc[mt][nt][2] + bz0;
            float v3 = acc[mt][nt][3] + bz1;
            if (gelu) {
                v0 = 0.5f * v0 * (1.f + erff(v0 * 0.70710678118654752f));
                v1 = 0.5f * v1 * (1.f + erff(v1 * 0.70710678118654752f));
                v2 = 0.5f * v2 * (1.f + erff(v2 * 0.70710678118654752f));
                v3 = 0.5f * v3 * (1.f + erff(v3 * 0.70710678118654752f));
            }
            *(float2*)(C + (size_t)r * N + cc)       = make_float2(v0, v1);
            *(float2*)(C + (size_t)(r + 8) * N + cc) = make_float2(v2, v3);
        }
    }
}

// ---------------- tf32 flash attention (batch 0) -----------------------------
// grid (SLEN/64, NHEAD), 128 threads = 4 warps. BQ=64 (16 rows/warp), BK=64.
// Q resident in registers as tf32 A-frags. P routed through padded smem.
#define PS_STRIDE 68
__global__ void __launch_bounds__(128) flash_tf32_kernel(
    const float* __restrict__ Q, const float* __restrict__ K,
    const float* __restrict__ V, float* __restrict__ O)
{
    extern __shared__ float sm[];
    float* Ks = sm;                    // [64][68]  key-major [key][feat]
    float* Vs = sm + 64 * PS_STRIDE;   // [64][68]  [key][feat]
    float* Ps = sm + 2 * 64 * PS_STRIDE; // [64][68] P tile / Q staging

    const int h  = blockIdx.y;
    const int q0 = blockIdx.x * 64;
    const int tid = threadIdx.x;
    const int warp = tid >> 5, lane = tid & 31;
    const int g = lane >> 2, c = lane & 3;
    const int wrow = warp * 16;

    // stage Q tile -> Ps (tf32), then load per-warp Q A-frags into registers
    const float* Qg = Q + (size_t)q0 * DMODEL + h * DH;
    for (int e = tid; e < 1024; e += 128) {
        int r = e >> 4, c4 = (e & 15) << 2;
        st4tf(&Ps[r * PS_STRIDE + c4], *(const float4*)(Qg + (size_t)r * DMODEL + c4));
    }
    __syncthreads();
    unsigned qa[8][4];
    #pragma unroll
    for (int kt = 0; kt < 8; ++kt) {
        const float* p = &Ps[(wrow + g) * PS_STRIDE + kt * 8 + c];
        qa[kt][0] = __float_as_uint(p[0]);
        qa[kt][1] = __float_as_uint(p[8 * PS_STRIDE]);
        qa[kt][2] = __float_as_uint(p[4]);
        qa[kt][3] = __float_as_uint(p[8 * PS_STRIDE + 4]);
    }

    float oacc[8][4];
    #pragma unroll
    for (int nt = 0; nt < 8; ++nt)
        #pragma unroll
        for (int i = 0; i < 4; ++i) oacc[nt][i] = 0.f;
    float m0 = -1e30f, m1 = -1e30f, l0 = 0.f, l1 = 0.f;

    const float* Kg = K + h * DH;
    const float* Vg = V + h * DH;

    for (int kt0 = 0; kt0 < SLEN; kt0 += 64) {
        __syncthreads();   // prior iter's Ks/Vs/Ps consumers done
        for (int e = tid; e < 1024; e += 128) {
            int r = e >> 4, c4 = (e & 15) << 2;
            st4tf(&Ks[r * PS_STRIDE + c4],
                  *(const float4*)(Kg + (size_t)(kt0 + r) * DMODEL + c4));
            st4tf(&Vs[r * PS_STRIDE + c4],
                  *(const float4*)(Vg + (size_t)(kt0 + r) * DMODEL + c4));
        }
        __syncthreads();

        // S = Q @ K^T  (warp rows x 64 keys)
        float sacc[8][4];
        #pragma unroll
        for (int nt = 0; nt < 8; ++nt)
            #pragma unroll
            for (int i = 0; i < 4; ++i) sacc[nt][i] = 0.f;
        #pragma unroll
        for (int kt = 0; kt < 8; ++kt) {
            #pragma unroll
            for (int nt = 0; nt < 8; ++nt) {
                const float* kp = &Ks[(nt * 8 + g) * PS_STRIDE + kt * 8 + c];
                unsigned b0 = __float_as_uint(kp[0]);
                unsigned b1 = __float_as_uint(kp[4]);
                mma_tf32(sacc[nt], qa[kt], b0, b1);
            }
        }

        // online softmax (rows g and g+8 of this warp's 16)
        float mx0 = -1e30f, mx1 = -1e30f;
        #pragma unroll
        for (int nt = 0; nt < 8; ++nt) {
            mx0 = fmaxf(mx0, fmaxf(sacc[nt][0], sacc[nt][1]));
            mx1 = fmaxf(mx1, fmaxf(sacc[nt][2], sacc[nt][3]));
        }
        mx0 = fmaxf(mx0, __shfl_xor_sync(0xffffffffu, mx0, 1));
        mx0 = fmaxf(mx0, __shfl_xor_sync(0xffffffffu, mx0, 2));
        mx1 = fmaxf(mx1, __shfl_xor_sync(0xffffffffu, mx1, 1));
        mx1 = fmaxf(mx1, __shfl_xor_sync(0xffffffffu, mx1, 2));
        float m0n = fmaxf(m0, mx0 * 0.125f);
        float m1n = fmaxf(m1, mx1 * 0.125f);
        float corr0 = __expf(m0 - m0n);
        float corr1 = __expf(m1 - m1n);

        float sum0 = 0.f, sum1 = 0.f;
        #pragma unroll
        for (int nt = 0; nt < 8; ++nt) {
            float p00 = __expf(sacc[nt][0] * 0.125f - m0n);
            float p01 = __expf(sacc[nt][1] * 0.125f - m0n);
            float p10 = __expf(sacc[nt][2] * 0.125f - m1n);
            float p11 = __expf(sacc[nt][3] * 0.125f - m1n);
            sum0 += p00 + p01;
            sum1 += p10 + p11;
            float2 lo = make_float2(__uint_as_float(f2tf(p00)), __uint_as_float(f2tf(p01)));
            float2 hi = make_float2(__uint_as_float(f2tf(p10)), __uint_as_float(f2tf(p11)));
            *(float2*)&Ps[(wrow + g)     * PS_STRIDE + nt * 8 + 2 * c] = lo;
            *(float2*)&Ps[(wrow + g + 8) * PS_STRIDE + nt * 8 + 2 * c] = hi;
        }
        sum0 += __shfl_xor_sync(0xffffffffu, sum0, 1);
        sum0 += __shfl_xor_sync(0xffffffffu, sum0, 2);
        sum1 += __shfl_xor_sync(0xffffffffu, sum1, 1);
        sum1 += __shfl_xor_sync(0xffffffffu, sum1, 2);
        m0 = m0n; m1 = m1n;
        l0 = l0 * corr0 + sum0;
        l1 = l1 * corr1 + sum1;
        #pragma unroll
        for (int nt = 0; nt < 8; ++nt) {
            oacc[nt][0] *= corr0; oacc[nt][1] *= corr0;
            oacc[nt][2] *= corr1; oacc[nt][3] *= corr1;
        }
        __syncwarp();

        // O += P @ V (warp-local P rows)
        #pragma unroll
        for (int kt = 0; kt < 8; ++kt) {
            unsigned a[4];
            const float* p = &Ps[(wrow + g) * PS_STRIDE + kt * 8 + c];
            a[0] = __float_as_uint(p[0]);
            a[1] = __float_as_uint(p[8 * PS_STRIDE]);
            a[2] = __float_as_uint(p[4]);
            a[3] = __float_as_uint(p[8 * PS_STRIDE + 4]);
            #pragma unroll
            for (int nt = 0; nt < 8; ++nt) {
                unsigned b0 = __float_as_uint(Vs[(kt * 8 + c)     * PS_STRIDE + nt * 8 + g]);
                unsigned b1 = __float_as_uint(Vs[(kt * 8 + c + 4) * PS_STRIDE + nt * 8 + g]);
                mma_tf32(oacc[nt], a, b0, b1);
            }
        }
    }

    float i0 = 1.f / l0, i1 = 1.f / l1;
    #pragma unroll
    for (int nt = 0; nt < 8; ++nt) {
        int cc = h * DH + nt * 8 + 2 * c;
        *(float2*)(O + (size_t)(q0 + wrow + g)     * DMODEL + cc) =
            make_float2(oacc[nt][0] * i0, oacc[nt][1] * i0);
        *(float2*)(O + (size_t)(q0 + wrow + g + 8) * DMODEL + cc) =
            make_float2(oacc[nt][2] * i1, oacc[nt][3] * i1);
    }
}

// ---------------- fused residual-add + LayerNorm ----------------------------
__global__ void __launch_bounds__(256) add_ln_kernel(
    const float* __restrict__ X, const float* __restrict__ Y,
    const float* __restrict__ g, const float* __restrict__ b,
    float* __restrict__ out, int ymod)
{
    const int row = blockIdx.x;
    const int tid = threadIdx.x;
    const float* xr = X + (size_t)row * DMODEL;
    const float* yr = Y + (size_t)(row % ymod) * DMODEL;

    float4 xv = *(const float4*)(xr + tid * 4);
    float4 yv = *(const float4*)(yr + tid * 4);
    float v0 = xv.x + yv.x, v1 = xv.y + yv.y, v2 = xv.z + yv.z, v3 = xv.w + yv.w;

    float sum = v0 + v1 + v2 + v3;
    float sq  = v0*v0 + v1*v1 + v2*v2 + v3*v3;
    #pragma unroll
    for (int off = 16; off; off >>= 1) {
        sum += __shfl_xor_sync(0xffffffffu, sum, off);
        sq  += __shfl_xor_sync(0xffffffffu, sq,  off);
    }
    __shared__ float ssum[8], ssq[8];
    int w = tid >> 5, lane = tid & 31;
    if (lane == 0) { ssum[w] = sum; ssq[w] = sq; }
    __syncthreads();
    if (tid == 0) {
        float ts = 0.f, tq = 0.f;
        #pragma unroll
        for (int i = 0; i < 8; ++i) { ts += ssum[i]; tq += ssq[i]; }
        ssum[0] = ts; ssq[0] = tq;
    }
    __syncthreads();
    const float mu   = ssum[0] * (1.f / DMODEL);
    const float var  = ssq[0] * (1.f / DMODEL) - mu * mu;
    const float rstd = rsqrtf(var + 1e-5f);

    int cc = tid * 4;
    float4 gv = *(const float4*)(g + cc);
    float4 bv = *(const float4*)(b + cc);
    float4 o;
    o.x = (v0 - mu) * rstd * gv.x + bv.x;
    o.y = (v1 - mu) * rstd * gv.y + bv.y;
    o.z = (v2 - mu) * rstd * gv.z + bv.z;
    o.w = (v3 - mu) * rstd * gv.w + bv.w;
    *(float4*)(out + (size_t)row * DMODEL + cc) = o;
}

// ---------------- launch -----------------------------------------------------
extern "C" void kernel_launch(void* const* d_in, const int* in_sizes, int n_in,
                              void* d_out, int out_size)
{
    const float* src    = (const float*)d_in[0];
    const float* w_q    = (const float*)d_in[1];
    const float* b_q    = (const float*)d_in[2];
    const float* w_k    = (const float*)d_in[3];
    const float* b_k    = (const float*)d_in[4];
    const float* w_v    = (const float*)d_in[5];
    const float* b_v    = (const float*)d_in[6];
    const float* w_out  = (const float*)d_in[7];
    const float* b_out  = (const float*)d_in[8];
    const float* ln1_g  = (const float*)d_in[9];
    const float* ln1_b  = (const float*)d_in[10];
    const float* ln2_g  = (const float*)d_in[11];
    const float* ln2_b  = (const float*)d_in[12];
    const float* ffn_w1 = (const float*)d_in[13];
    const float* ffn_b1 = (const float*)d_in[14];
    const float* ffn_w2 = (const float*)d_in[15];
    const float* ffn_b2 = (const float*)d_in[16];
    float* out = (float*)d_out;

    float *pq, *pk, *pv, *pctx, *pattn, *px, *pf1, *pf2;
    cudaGetSymbolAddress((void**)&pq,    g_q);
    cudaGetSymbolAddress((void**)&pk,    g_k);
    cudaGetSymbolAddress((void**)&pv,    g_v);
    cudaGetSymbolAddress((void**)&pctx,  g_ctx);
    cudaGetSymbolAddress((void**)&pattn, g_attn);
    cudaGetSymbolAddress((void**)&px,    g_x);
    cudaGetSymbolAddress((void**)&pf1,   g_ffn1);
    cudaGetSymbolAddress((void**)&pf2,   g_ffn2);

    const size_t attn_smem = 3 * 64 * PS_STRIDE * sizeof(float);  // 52224 B
    cudaFuncSetAttribute(flash_tf32_kernel,
                         cudaFuncAttributeMaxDynamicSharedMemorySize,
                         (int)attn_smem);

    dim3 blk(256);

    // QKV projections (batch 0 only)
    dim3 g_qkv(DMODEL / 128, ROWS_B0 / 128);
    gemm_tf32_kernel<<<g_qkv, blk>>>(src, w_q, b_q, pq, ROWS_B0, DMODEL, DMODEL, 0);
    gemm_tf32_kernel<<<g_qkv, blk>>>(src, w_k, b_k, pk, ROWS_B0, DMODEL, DMODEL, 0);
    gemm_tf32_kernel<<<g_qkv, blk>>>(src, w_v, b_v, pv, ROWS_B0, DMODEL, DMODEL, 0);

    // attention (batch 0)
    dim3 g_att(SLEN / 64, NHEAD);
    flash_tf32_kernel<<<g_att, dim3(128), attn_smem>>>(pq, pk, pv, pctx);

    // output projection
    gemm_tf32_kernel<<<g_qkv, blk>>>(pctx, w_out, b_out, pattn, ROWS_B0, DMODEL, DMODEL, 0);

    // x = LN1(src + attn_out[0] broadcast)
    add_ln_kernel<<<ROWS_ALL, blk>>>(src, pattn, ln1_g, ln1_b, px, SLEN);

    // FFN
    dim3 g_f1(DFF / 128,    ROWS_ALL / 128);
    dim3 g_f2(DMODEL / 128, ROWS_ALL / 128);
    gemm_tf32_kernel<<<g_f1, blk>>>(px,  ffn_w1, ffn_b1, pf1, ROWS_ALL, DFF,    DMODEL, 1);
    gemm_tf32_kernel<<<g_f2, blk>>>(pf1, ffn_w2, ffn_b2, pf2, ROWS_ALL, DMODEL, DFF,    0);

    // out = LN2(x + ffn)
    add_ln_kernel<<<ROWS_ALL, blk>>>(px, pf2, ln2_g, ln2_b, out, ROWS_ALL);
}

// round 5
// speedup vs baseline: 10.0614x; 2.1185x over previous
#include <cuda_runtime.h>
#include <cuda_fp16.h>
#include <math.h>
#include <stdint.h>

// Problem constants
#define BATCH 2
#define SLEN  2048
#define DMODEL 1024
#define NHEAD 16
#define DH    64
#define DFF   2048
#define ROWS_B0   (SLEN)
#define ROWS_ALL  (BATCH*SLEN)

// ---------------- scratch (static device globals; no allocs) ----------------
__device__ __half hh_src[SLEN*DMODEL];
__device__ __half hh_q  [SLEN*DMODEL];
__device__ __half hh_k  [SLEN*DMODEL];
__device__ __half hh_v  [SLEN*DMODEL];
__device__ __half hh_ctx[SLEN*DMODEL];
__device__ float  g_attn[SLEN*DMODEL];
__device__ float  g_x   [ROWS_ALL*DMODEL];
__device__ __half hh_x  [ROWS_ALL*DMODEL];
__device__ __half hh_f1 [ROWS_ALL*DFF];
__device__ float  g_f2  [ROWS_ALL*DMODEL];
// transposed+converted weights ([N][K] half)
__device__ __half hh_wq[DMODEL*DMODEL];
__device__ __half hh_wk[DMODEL*DMODEL];
__device__ __half hh_wv[DMODEL*DMODEL];
__device__ __half hh_wo[DMODEL*DMODEL];
__device__ __half hh_w1[DFF*DMODEL];
__device__ __half hh_w2[DMODEL*DFF];

// ---------------- helpers ----------------------------------------------------
__device__ __forceinline__ uint32_t smem_u32(const void* p) {
    uint32_t a;
    asm("{ .reg .u64 t; cvta.to.shared.u64 t, %1; cvt.u32.u64 %0, t; }"
        : "=r"(a) : "l"(p));
    return a;
}
__device__ __forceinline__ void ldm_x4(unsigned r[4], uint32_t addr) {
    asm volatile("ldmatrix.sync.aligned.m8n8.x4.shared.b16 {%0,%1,%2,%3}, [%4];"
        : "=r"(r[0]), "=r"(r[1]), "=r"(r[2]), "=r"(r[3]) : "r"(addr));
}
__device__ __forceinline__ void ldm_x4_t(unsigned r[4], uint32_t addr) {
    asm volatile("ldmatrix.sync.aligned.m8n8.x4.trans.shared.b16 {%0,%1,%2,%3}, [%4];"
        : "=r"(r[0]), "=r"(r[1]), "=r"(r[2]), "=r"(r[3]) : "r"(addr));
}
__device__ __forceinline__ void mma16(float c[4], const unsigned a[4],
                                      unsigned b0, unsigned b1) {
    asm volatile(
        "mma.sync.aligned.m16n8k16.row.col.f32.f16.f16.f32 "
        "{%0,%1,%2,%3},{%4,%5,%6,%7},{%8,%9},{%0,%1,%2,%3};"
        : "+f"(c[0]), "+f"(c[1]), "+f"(c[2]), "+f"(c[3])
        : "r"(a[0]), "r"(a[1]), "r"(a[2]), "r"(a[3]), "r"(b0), "r"(b1));
}
#define CP_ASYNC16(dst, src) \
    asm volatile("cp.async.cg.shared.global [%0], [%1], 16;" :: "r"(dst), "l"(src))
#define CP_COMMIT() asm volatile("cp.async.commit_group;")
#define CP_WAIT1()  asm volatile("cp.async.wait_group 1;")

// ---------------- converters -------------------------------------------------
__global__ void __launch_bounds__(256) f32_to_f16_kernel(
    const float* __restrict__ in, __half* __restrict__ out, int n)
{
    int i = (blockIdx.x * 256 + threadIdx.x) * 4;
    if (i < n) {
        float4 v = *(const float4*)(in + i);
        *(__half2*)(out + i)     = __floats2half2_rn(v.x, v.y);
        *(__half2*)(out + i + 2) = __floats2half2_rn(v.z, v.w);
    }
}
// out[C][R] = (half) in[R][C]^T
__global__ void __launch_bounds__(256) transpose_f16_kernel(
    const float* __restrict__ in, __half* __restrict__ out, int R, int C)
{
    __shared__ float t[32][33];
    int bx = blockIdx.x * 32, by = blockIdx.y * 32;
    int tx = threadIdx.x, ty = threadIdx.y;
    #pragma unroll
    for (int i = ty; i < 32; i += 8)
        t[i][tx] = in[(size_t)(by + i) * C + bx + tx];
    __syncthreads();
    #pragma unroll
    for (int i = ty; i < 32; i += 8)
        out[(size_t)(bx + i) * R + by + tx] = __float2half(t[tx][i]);
}

// ---------------- fp16 tensor-core GEMM --------------------------------------
// C[M,N] = A[M,K] @ Bt[N,K]^T + bias (+optional exact GELU)
// A, Bt half in gmem. 128x128 tile, K-tile 64, 256 thr = 8 warps (4M x 2N),
// warp tile 32x64 (2 Mtile16 x 8 Ntile8), cp.async 2-stage pipeline.
#define HST 72                      // halves per smem row (144B, conflict-free)
#define OP_BYTES (128*HST*2)        // 18432 per operand per stage
#define GEMM_SMEM (4*OP_BYTES)      // 73728

__global__ void __launch_bounds__(256) gemm_fp16_kernel(
    const __half* __restrict__ A,
    const __half* __restrict__ B0, const __half* __restrict__ B1, const __half* __restrict__ B2,
    const float* __restrict__ bias0, const float* __restrict__ bias1, const float* __restrict__ bias2,
    float* __restrict__ C0, float* __restrict__ C1, float* __restrict__ C2,
    __half* __restrict__ H0, __half* __restrict__ H1, __half* __restrict__ H2,
    int M, int N, int K, int gelu)
{
    extern __shared__ __half sm[];
    const int z = blockIdx.z;
    const __half* Bt  = (z == 0) ? B0 : (z == 1) ? B1 : B2;
    const float* bias = (z == 0) ? bias0 : (z == 1) ? bias1 : bias2;
    float*  C = (z == 0) ? C0 : (z == 1) ? C1 : C2;
    __half* H = (z == 0) ? H0 : (z == 1) ? H1 : H2;

    const int tid = threadIdx.x, lane = tid & 31, warp = tid >> 5;
    const int wm = warp >> 1, wn = warp & 1;
    const int row0 = blockIdx.y * 128, col0 = blockIdx.x * 128;

    uint32_t smb = smem_u32(sm);
    uint32_t aB[2] = { smb,            smb + 2 * OP_BYTES };
    uint32_t bB[2] = { smb + OP_BYTES, smb + 3 * OP_BYTES };

    float acc[2][8][4];
    #pragma unroll
    for (int mt = 0; mt < 2; ++mt)
        #pragma unroll
        for (int nt = 0; nt < 8; ++nt)
            #pragma unroll
            for (int i = 0; i < 4; ++i) acc[mt][nt][i] = 0.f;

    const int aRow = wm * 32 + (lane & 15);
    const int aCol = (lane >> 4) * 8;
    const int quad = lane >> 3, ql = lane & 7;
    const int bRowB = wn * 64 + ((quad >> 1) << 3) + ql;   // + pr*16
    const int bColB = (quad & 1) * 8;                      // + ks*16

    const int nk = K >> 6;   // K/64

    // pipeline: stage s -> buf s&1
    #pragma unroll 1
    for (int p = 0; p < 2; ++p) {
        int k0 = p * 64;
        #pragma unroll
        for (int i = 0; i < 4; ++i) {
            int idx = tid + i * 256;
            int r = idx >> 3, ch = idx & 7;
            CP_ASYNC16(aB[p] + r * 144 + ch * 16, A  + (size_t)(row0 + r) * K + k0 + ch * 8);
            CP_ASYNC16(bB[p] + r * 144 + ch * 16, Bt + (size_t)(col0 + r) * K + k0 + ch * 8);
        }
        CP_COMMIT();
    }

    for (int s = 0; s < nk; ++s) {
        CP_WAIT1();
        __syncthreads();
        const int buf = s & 1;
        #pragma unroll
        for (int ks = 0; ks < 4; ++ks) {
            unsigned af0[4], af1[4];
            ldm_x4(af0, aB[buf] + aRow * 144 + (ks * 16 + aCol) * 2);
            ldm_x4(af1, aB[buf] + (aRow + 16) * 144 + (ks * 16 + aCol) * 2);
            #pragma unroll
            for (int pr = 0; pr < 4; ++pr) {
                unsigned bf[4];
                ldm_x4(bf, bB[buf] + (bRowB + pr * 16) * 144 + (ks * 16 + bColB) * 2);
                mma16(acc[0][2 * pr],     af0, bf[0], bf[1]);
                mma16(acc[0][2 * pr + 1], af0, bf[2], bf[3]);
                mma16(acc[1][2 * pr],     af1, bf[0], bf[1]);
                mma16(acc[1][2 * pr + 1], af1, bf[2], bf[3]);
            }
        }
        __syncthreads();
        if (s + 2 < nk) {
            int k0 = (s + 2) * 64;
            #pragma unroll
            for (int i = 0; i < 4; ++i) {
                int idx = tid + i * 256;
                int r = idx >> 3, ch = idx & 7;
                CP_ASYNC16(aB[buf] + r * 144 + ch * 16, A  + (size_t)(row0 + r) * K + k0 + ch * 8);
                CP_ASYNC16(bB[buf] + r * 144 + ch * 16, Bt + (size_t)(col0 + r) * K + k0 + ch * 8);
            }
        }
        CP_COMMIT();
    }

    // epilogue
    const int g = lane >> 2, c4 = lane & 3;
    #pragma unroll
    for (int mt = 0; mt < 2; ++mt) {
        int r = row0 + wm * 32 + mt * 16 + g;
        #pragma unroll
        for (int nt = 0; nt < 8; ++nt) {
            int cc = col0 + wn * 64 + nt * 8 + 2 * c4;
            float bz0 = bias[cc], bz1 = bias[cc + 1];
            float v0 = acc[mt][nt][0] + bz0;
            float v1 = acc[mt][nt][1] + bz1;
            float v2 = acc[mt][nt][2] + bz0;
            float v3 = acc[mt][nt][3] + bz1;
            if (gelu) {
                v0 = 0.5f * v0 * (1.f + erff(v0 * 0.70710678118654752f));
                v1 = 0.5f * v1 * (1.f + erff(v1 * 0.70710678118654752f));
                v2 = 0.5f * v2 * (1.f + erff(v2 * 0.70710678118654752f));
                v3 = 0.5f * v3 * (1.f + erff(v3 * 0.70710678118654752f));
            }
            if (C) {
                *(float2*)(C + (size_t)r * N + cc)       = make_float2(v0, v1);
                *(float2*)(C + (size_t)(r + 8) * N + cc) = make_float2(v2, v3);
            }
            if (H) {
                *(__half2*)(H + (size_t)r * N + cc)       = __floats2half2_rn(v0, v1);
                *(__half2*)(H + (size_t)(r + 8) * N + cc) = __floats2half2_rn(v2, v3);
            }
        }
    }
}

// ---------------- fp16 flash attention (batch 0) -----------------------------
// grid (SLEN/64, NHEAD), 128 thr = 4 warps, warp owns 16 q-rows. BK=64.
// Q frags register-resident; K/V double-buffered via cp.async; V via ldmatrix.trans.
__global__ void __launch_bounds__(128) flash_fp16_kernel(
    const __half* __restrict__ Q, const __half* __restrict__ K,
    const __half* __restrict__ V, __half* __restrict__ O)
{
    __shared__ __half Ks[2][64 * HST];
    __shared__ __half Vs[2][64 * HST];
    __shared__ __half Ps[64 * HST];

    const int h = blockIdx.y, q0 = blockIdx.x * 64;
    const int tid = threadIdx.x, lane = tid & 31, warp = tid >> 5;
    const int wrow = warp * 16;
    const int g = lane >> 2, c4 = lane & 3;

    uint32_t ksb[2] = { smem_u32(Ks[0]), smem_u32(Ks[1]) };
    uint32_t vsb[2] = { smem_u32(Vs[0]), smem_u32(Vs[1]) };
    uint32_t psb = smem_u32(Ps);

    const __half* Qg = Q + (size_t)q0 * DMODEL + h * DH;
    const __half* Kg = K + h * DH;
    const __half* Vg = V + h * DH;

    // stage Q tile into Ps, then load per-warp A-frags to registers
    #pragma unroll
    for (int i = 0; i < 4; ++i) {
        int idx = tid + i * 128;
        int r = idx >> 3, ch = idx & 7;
        *(uint4*)(Ps + r * HST + ch * 8) = *(const uint4*)(Qg + (size_t)r * DMODEL + ch * 8);
    }
    __syncthreads();
    const int aRow = wrow + (lane & 15);
    const int aCol = (lane >> 4) * 8;
    unsigned qa[4][4];
    #pragma unroll
    for (int ks = 0; ks < 4; ++ks)
        ldm_x4(qa[ks], psb + aRow * 144 + (ks * 16 + aCol) * 2);

    float oacc[8][4];
    #pragma unroll
    for (int nt = 0; nt < 8; ++nt)
        #pragma unroll
        for (int i = 0; i < 4; ++i) oacc[nt][i] = 0.f;
    float m0 = -1e30f, m1 = -1e30f, l0 = 0.f, l1 = 0.f;

    const int quad = lane >> 3, ql = lane & 7;
    const int bRowS = ((quad >> 1) << 3) + ql;   // + pr*16 ; cols ks*16 + bColS
    const int bColS = (quad & 1) * 8;
    const int vRow  = (quad & 1) * 8 + ql;       // + ks*16 ; cols pr*16 + vCol
    const int vCol  = (quad >> 1) * 8;

    // prologue loads (stages 0,1)
    #pragma unroll 1
    for (int p = 0; p < 2; ++p) {
        int s0 = p * 64;
        #pragma unroll
        for (int i = 0; i < 8; ++i) {
            int idx = tid + i * 128;
            if (idx < 512) {
                int r = idx >> 3, ch = idx & 7;
                CP_ASYNC16(ksb[p] + r * 144 + ch * 16, Kg + (size_t)(s0 + r) * DMODEL + ch * 8);
            } else {
                int j = idx - 512; int r = j >> 3, ch = j & 7;
                CP_ASYNC16(vsb[p] + r * 144 + ch * 16, Vg + (size_t)(s0 + r) * DMODEL + ch * 8);
            }
        }
        CP_COMMIT();
    }

    for (int kt = 0; kt < SLEN / 64; ++kt) {
        CP_WAIT1();
        __syncthreads();
        const int buf = kt & 1;

        // S = Q @ K^T
        float sacc[8][4];
        #pragma unroll
        for (int nt = 0; nt < 8; ++nt)
            #pragma unroll
            for (int i = 0; i < 4; ++i) sacc[nt][i] = 0.f;
        #pragma unroll
        for (int ks = 0; ks < 4; ++ks) {
            #pragma unroll
            for (int pr = 0; pr < 4; ++pr) {
                unsigned bf[4];
                ldm_x4(bf, ksb[buf] + (bRowS + pr * 16) * 144 + (ks * 16 + bColS) * 2);
                mma16(sacc[2 * pr],     qa[ks], bf[0], bf[1]);
                mma16(sacc[2 * pr + 1], qa[ks], bf[2], bf[3]);
            }
        }

        // online softmax (rows g and g+8 of the warp's 16)
        float mx0 = -1e30f, mx1 = -1e30f;
        #pragma unroll
        for (int nt = 0; nt < 8; ++nt) {
            mx0 = fmaxf(mx0, fmaxf(sacc[nt][0], sacc[nt][1]));
            mx1 = fmaxf(mx1, fmaxf(sacc[nt][2], sacc[nt][3]));
        }
        mx0 = fmaxf(mx0, __shfl_xor_sync(0xffffffffu, mx0, 1));
        mx0 = fmaxf(mx0, __shfl_xor_sync(0xffffffffu, mx0, 2));
        mx1 = fmaxf(mx1, __shfl_xor_sync(0xffffffffu, mx1, 1));
        mx1 = fmaxf(mx1, __shfl_xor_sync(0xffffffffu, mx1, 2));
        float m0n = fmaxf(m0, mx0 * 0.125f);
        float m1n = fmaxf(m1, mx1 * 0.125f);
        float corr0 = __expf(m0 - m0n);
        float corr1 = __expf(m1 - m1n);

        float sum0 = 0.f, sum1 = 0.f;
        #pragma unroll
        for (int nt = 0; nt < 8; ++nt) {
            float p00 = __expf(sacc[nt][0] * 0.125f - m0n);
            float p01 = __expf(sacc[nt][1] * 0.125f - m0n);
            float p10 = __expf(sacc[nt][2] * 0.125f - m1n);
            float p11 = __expf(sacc[nt][3] * 0.125f - m1n);
            sum0 += p00 + p01;
            sum1 += p10 + p11;
            *(__half2*)(Ps + (wrow + g)     * HST + nt * 8 + 2 * c4) = __floats2half2_rn(p00, p01);
            *(__half2*)(Ps + (wrow + g + 8) * HST + nt * 8 + 2 * c4) = __floats2half2_rn(p10, p11);
        }
        sum0 += __shfl_xor_sync(0xffffffffu, sum0, 1);
        sum0 += __shfl_xor_sync(0xffffffffu, sum0, 2);
        sum1 += __shfl_xor_sync(0xffffffffu, sum1, 1);
        sum1 += __shfl_xor_sync(0xffffffffu, sum1, 2);
        m0 = m0n; m1 = m1n;
        l0 = l0 * corr0 + sum0;
        l1 = l1 * corr1 + sum1;
        #pragma unroll
        for (int nt = 0; nt < 8; ++nt) {
            oacc[nt][0] *= corr0; oacc[nt][1] *= corr0;
            oacc[nt][2] *= corr1; oacc[nt][3] *= corr1;
        }
        __syncwarp();

        // O += P @ V
        #pragma unroll
        for (int ks = 0; ks < 4; ++ks) {
            unsigned pf[4];
            ldm_x4(pf, psb + aRow * 144 + (ks * 16 + aCol) * 2);
            #pragma unroll
            for (int pr = 0; pr < 4; ++pr) {
                unsigned bf[4];
                ldm_x4_t(bf, vsb[buf] + (vRow + ks * 16) * 144 + (vCol + pr * 16) * 2);
                mma16(oacc[2 * pr],     pf, bf[0], bf[1]);
                mma16(oacc[2 * pr + 1], pf, bf[2], bf[3]);
            }
        }
        __syncthreads();

        if (kt + 2 < SLEN / 64) {
            int s0 = (kt + 2) * 64;
            #pragma unroll
            for (int i = 0; i < 8; ++i) {
                int idx = tid + i * 128;
                if (idx < 512) {
                    int r = idx >> 3, ch = idx & 7;
                    CP_ASYNC16(ksb[buf] + r * 144 + ch * 16, Kg + (size_t)(s0 + r) * DMODEL + ch * 8);
                } else {
                    int j = idx - 512; int r = j >> 3, ch = j & 7;
                    CP_ASYNC16(vsb[buf] + r * 144 + ch * 16, Vg + (size_t)(s0 + r) * DMODEL + ch * 8);
                }
            }
        }
        CP_COMMIT();
    }

    float i0 = 1.f / l0, i1 = 1.f / l1;
    #pragma unroll
    for (int nt = 0; nt < 8; ++nt) {
        int cc = h * DH + nt * 8 + 2 * c4;
        *(__half2*)(O + (size_t)(q0 + wrow + g)     * DMODEL + cc) =
            __floats2half2_rn(oacc[nt][0] * i0, oacc[nt][1] * i0);
        *(__half2*)(O + (size_t)(q0 + wrow + g + 8) * DMODEL + cc) =
            __floats2half2_rn(oacc[nt][2] * i1, oacc[nt][3] * i1);
    }
}

// ---------------- fused residual-add + LayerNorm (+ optional half copy) ------
__global__ void __launch_bounds__(256) add_ln_kernel(
    const float* __restrict__ X, const float* __restrict__ Y,
    const float* __restrict__ g, const float* __restrict__ b,
    float* __restrict__ out, __half* __restrict__ outh, int ymod)
{
    const int row = blockIdx.x;
    const int tid = threadIdx.x;
    const float* xr = X + (size_t)row * DMODEL;
    const float* yr = Y + (size_t)(row % ymod) * DMODEL;

    float4 xv = *(const float4*)(xr + tid * 4);
    float4 yv = *(const float4*)(yr + tid * 4);
    float v0 = xv.x + yv.x, v1 = xv.y + yv.y, v2 = xv.z + yv.z, v3 = xv.w + yv.w;

    float sum = v0 + v1 + v2 + v3;
    float sq  = v0*v0 + v1*v1 + v2*v2 + v3*v3;
    #pragma unroll
    for (int off = 16; off; off >>= 1) {
        sum += __shfl_xor_sync(0xffffffffu, sum, off);
        sq  += __shfl_xor_sync(0xffffffffu, sq,  off);
    }
    __shared__ float ssum[8], ssq[8];
    int w = tid >> 5, lane = tid & 31;
    if (lane == 0) { ssum[w] = sum; ssq[w] = sq; }
    __syncthreads();
    if (tid == 0) {
        float ts = 0.f, tq = 0.f;
        #pragma unroll
        for (int i = 0; i < 8; ++i) { ts += ssum[i]; tq += ssq[i]; }
        ssum[0] = ts; ssq[0] = tq;
    }
    __syncthreads();
    const float mu   = ssum[0] * (1.f / DMODEL);
    const float var  = ssq[0] * (1.f / DMODEL) - mu * mu;
    const float rstd = rsqrtf(var + 1e-5f);

    int cc = tid * 4;
    float4 gv = *(const float4*)(g + cc);
    float4 bv = *(const float4*)(b + cc);
    float4 o;
    o.x = (v0 - mu) * rstd * gv.x + bv.x;
    o.y = (v1 - mu) * rstd * gv.y + bv.y;
    o.z = (v2 - mu) * rstd * gv.z + bv.z;
    o.w = (v3 - mu) * rstd * gv.w + bv.w;
    *(float4*)(out + (size_t)row * DMODEL + cc) = o;
    if (outh) {
        *(__half2*)(outh + (size_t)row * DMODEL + cc)     = __floats2half2_rn(o.x, o.y);
        *(__half2*)(outh + (size_t)row * DMODEL + cc + 2) = __floats2half2_rn(o.z, o.w);
    }
}

// ---------------- launch -----------------------------------------------------
extern "C" void kernel_launch(void* const* d_in, const int* in_sizes, int n_in,
                              void* d_out, int out_size)
{
    const float* src    = (const float*)d_in[0];
    const float* w_q    = (const float*)d_in[1];
    const float* b_q    = (const float*)d_in[2];
    const float* w_k    = (const float*)d_in[3];
    const float* b_k    = (const float*)d_in[4];
    const float* w_v    = (const float*)d_in[5];
    const float* b_v    = (const float*)d_in[6];
    const float* w_out  = (const float*)d_in[7];
    const float* b_out  = (const float*)d_in[8];
    const float* ln1_g  = (const float*)d_in[9];
    const float* ln1_b  = (const float*)d_in[10];
    const float* ln2_g  = (const float*)d_in[11];
    const float* ln2_b  = (const float*)d_in[12];
    const float* ffn_w1 = (const float*)d_in[13];
    const float* ffn_b1 = (const float*)d_in[14];
    const float* ffn_w2 = (const float*)d_in[15];
    const float* ffn_b2 = (const float*)d_in[16];
    float* out = (float*)d_out;

    __half *psrc, *pq, *pk, *pv, *pctx, *pxh, *pf1;
    __half *pwq, *pwk, *pwv, *pwo, *pw1, *pw2;
    float *pattn, *px, *pf2;
    cudaGetSymbolAddress((void**)&psrc, hh_src);
    cudaGetSymbolAddress((void**)&pq,   hh_q);
    cudaGetSymbolAddress((void**)&pk,   hh_k);
    cudaGetSymbolAddress((void**)&pv,   hh_v);
    cudaGetSymbolAddress((void**)&pctx, hh_ctx);
    cudaGetSymbolAddress((void**)&pxh,  hh_x);
    cudaGetSymbolAddress((void**)&pf1,  hh_f1);
    cudaGetSymbolAddress((void**)&pwq,  hh_wq);
    cudaGetSymbolAddress((void**)&pwk,  hh_wk);
    cudaGetSymbolAddress((void**)&pwv,  hh_wv);
    cudaGetSymbolAddress((void**)&pwo,  hh_wo);
    cudaGetSymbolAddress((void**)&pw1,  hh_w1);
    cudaGetSymbolAddress((void**)&pw2,  hh_w2);
    cudaGetSymbolAddress((void**)&pattn, g_attn);
    cudaGetSymbolAddress((void**)&px,    g_x);
    cudaGetSymbolAddress((void**)&pf2,   g_f2);

    cudaFuncSetAttribute(gemm_fp16_kernel,
                         cudaFuncAttributeMaxDynamicSharedMemorySize, GEMM_SMEM);

    // 1) convert+transpose weights, convert src (batch 0)
    dim3 tb(32, 8);
    transpose_f16_kernel<<<dim3(DMODEL/32, DMODEL/32), tb>>>(w_q,    pwq, DMODEL, DMODEL);
    transpose_f16_kernel<<<dim3(DMODEL/32, DMODEL/32), tb>>>(w_k,    pwk, DMODEL, DMODEL);
    transpose_f16_kernel<<<dim3(DMODEL/32, DMODEL/32), tb>>>(w_v,    pwv, DMODEL, DMODEL);
    transpose_f16_kernel<<<dim3(DMODEL/32, DMODEL/32), tb>>>(w_out,  pwo, DMODEL, DMODEL);
    transpose_f16_kernel<<<dim3(DFF/32,    DMODEL/32), tb>>>(ffn_w1, pw1, DMODEL, DFF);
    transpose_f16_kernel<<<dim3(DMODEL/32, DFF/32),    tb>>>(ffn_w2, pw2, DFF,    DMODEL);
    f32_to_f16_kernel<<<(SLEN*DMODEL/4 + 255)/256, 256>>>(src, psrc, SLEN*DMODEL);

    // 2) fused QKV projections (batch 0), grid.z = 3, half outputs
    gemm_fp16_kernel<<<dim3(DMODEL/128, ROWS_B0/128, 3), 256, GEMM_SMEM>>>(
        psrc, pwq, pwk, pwv, b_q, b_k, b_v,
        (float*)0, (float*)0, (float*)0, pq, pk, pv,
        ROWS_B0, DMODEL, DMODEL, 0);

    // 3) attention (batch 0)
    flash_fp16_kernel<<<dim3(SLEN/64, NHEAD), 128>>>(pq, pk, pv, pctx);

    // 4) output projection -> f32
    gemm_fp16_kernel<<<dim3(DMODEL/128, ROWS_B0/128, 1), 256, GEMM_SMEM>>>(
        pctx, pwo, pwo, pwo, b_out, b_out, b_out,
        pattn, pattn, pattn, (__half*)0, (__half*)0, (__half*)0,
        ROWS_B0, DMODEL, DMODEL, 0);

    // 5) x = LN1(src + attn_out[0] broadcast)  -> f32 + half
    add_ln_kernel<<<ROWS_ALL, 256>>>(src, pattn, ln1_g, ln1_b, px, pxh, SLEN);

    // 6) FFN1 (+GELU) -> half
    gemm_fp16_kernel<<<dim3(DFF/128, ROWS_ALL/128, 1), 256, GEMM_SMEM>>>(
        pxh, pw1, pw1, pw1, ffn_b1, ffn_b1, ffn_b1,
        (float*)0, (float*)0, (float*)0, pf1, pf1, pf1,
        ROWS_ALL, DFF, DMODEL, 1);

    // 7) FFN2 -> f32
    gemm_fp16_kernel<<<dim3(DMODEL/128, ROWS_ALL/128, 1), 256, GEMM_SMEM>>>(
        pf1, pw2, pw2, pw2, ffn_b2, ffn_b2, ffn_b2,
        pf2, pf2, pf2, (__half*)0, (__half*)0, (__half*)0,
        ROWS_ALL, DMODEL, DFF, 0);

    // 8) out = LN2(x + ffn)
    add_ln_kernel<<<ROWS_ALL, 256>>>(px, pf2, ln2_g, ln2_b, out, (__half*)0, ROWS_ALL);
}

// round 7
// speedup vs baseline: 10.6953x; 1.0630x over previous
#include <cuda_runtime.h>
#include <cuda_fp16.h>
#include <math.h>
#include <stdint.h>

// Problem constants
#define BATCH 2
#define SLEN  2048
#define DMODEL 1024
#define NHEAD 16
#define DH    64
#define DFF   2048
#define ROWS_B0   (SLEN)
#define ROWS_ALL  (BATCH*SLEN)

// ---------------- scratch (static device globals; no allocs) ----------------
__device__ __half hh_src[SLEN*DMODEL];
__device__ __half hh_q  [SLEN*DMODEL];
__device__ __half hh_k  [SLEN*DMODEL];
__device__ __half hh_v  [SLEN*DMODEL];
__device__ __half hh_ctx[SLEN*DMODEL];
__device__ float  g_attn[SLEN*DMODEL];
__device__ float  g_x   [ROWS_ALL*DMODEL];
__device__ __half hh_x  [ROWS_ALL*DMODEL];
__device__ __half hh_f1 [ROWS_ALL*DFF];
__device__ float  g_f2  [ROWS_ALL*DMODEL];
// transposed+converted weights ([N][K] half)
__device__ __half hh_wq[DMODEL*DMODEL];
__device__ __half hh_wk[DMODEL*DMODEL];
__device__ __half hh_wv[DMODEL*DMODEL];
__device__ __half hh_wo[DMODEL*DMODEL];
__device__ __half hh_w1[DFF*DMODEL];
__device__ __half hh_w2[DMODEL*DFF];

// ---------------- helpers ----------------------------------------------------
__device__ __forceinline__ uint32_t smem_u32(const void* p) {
    uint32_t a;
    asm("{ .reg .u64 t; cvta.to.shared.u64 t, %1; cvt.u32.u64 %0, t; }"
        : "=r"(a) : "l"(p));
    return a;
}
__device__ __forceinline__ void ldm_x4(unsigned r[4], uint32_t addr) {
    asm volatile("ldmatrix.sync.aligned.m8n8.x4.shared.b16 {%0,%1,%2,%3}, [%4];"
        : "=r"(r[0]), "=r"(r[1]), "=r"(r[2]), "=r"(r[3]) : "r"(addr));
}
__device__ __forceinline__ void ldm_x4_t(unsigned r[4], uint32_t addr) {
    asm volatile("ldmatrix.sync.aligned.m8n8.x4.trans.shared.b16 {%0,%1,%2,%3}, [%4];"
        : "=r"(r[0]), "=r"(r[1]), "=r"(r[2]), "=r"(r[3]) : "r"(addr));
}
__device__ __forceinline__ void mma16(float c[4], const unsigned a[4],
                                      unsigned b0, unsigned b1) {
    asm volatile(
        "mma.sync.aligned.m16n8k16.row.col.f32.f16.f16.f32 "
        "{%0,%1,%2,%3},{%4,%5,%6,%7},{%8,%9},{%0,%1,%2,%3};"
        : "+f"(c[0]), "+f"(c[1]), "+f"(c[2]), "+f"(c[3])
        : "r"(a[0]), "r"(a[1]), "r"(a[2]), "r"(a[3]), "r"(b0), "r"(b1));
}
#define CP_ASYNC16(dst, src) \
    asm volatile("cp.async.cg.shared.global [%0], [%1], 16;" :: "r"(dst), "l"(src))
#define CP_COMMIT() asm volatile("cp.async.commit_group;")
#define CP_WAIT1()  asm volatile("cp.async.wait_group 1;")

// ---------------- fused prep: 6 weight transposes + src f32->f16 -------------
// flat grid of 10240 blocks x 256 threads:
//   [0,4096):  wq/wk/wv/wo transposes (1024 blocks each, 32x32 tiles)
//   [4096,6144): ffn_w1 transpose  (R=1024,C=2048)
//   [6144,8192): ffn_w2 transpose  (R=2048,C=1024)
//   [8192,10240): src convert (2M halves)
__global__ void __launch_bounds__(256) prep_kernel(
    const float* __restrict__ src,
    const float* __restrict__ wq, const float* __restrict__ wk,
    const float* __restrict__ wv, const float* __restrict__ wo,
    const float* __restrict__ w1, const float* __restrict__ w2,
    __half* __restrict__ hsrc,
    __half* __restrict__ hwq, __half* __restrict__ hwk,
    __half* __restrict__ hwv, __half* __restrict__ hwo,
    __half* __restrict__ hw1, __half* __restrict__ hw2)
{
    __shared__ float t[32][33];
    const int b = blockIdx.x;
    const float* in; __half* outp; int R, C, bxi, byi;
    if (b < 4096) {
        int seg = b >> 10, lb = b & 1023;
        in   = (seg == 0) ? wq  : (seg == 1) ? wk  : (seg == 2) ? wv  : wo;
        outp = (seg == 0) ? hwq : (seg == 1) ? hwk : (seg == 2) ? hwv : hwo;
        R = 1024; C = 1024; bxi = lb & 31; byi = lb >> 5;
    } else if (b < 6144) {
        int lb = b - 4096; in = w1; outp = hw1; R = 1024; C = 2048;
        bxi = lb & 63; byi = lb >> 6;
    } else if (b < 8192) {
        int lb = b - 6144; in = w2; outp = hw2; R = 2048; C = 1024;
        bxi = lb & 31; byi = lb >> 5;
    } else {
        int lb = b - 8192;
        int i = (lb * 256 + threadIdx.x) * 4;
        float4 v = *(const float4*)(src + i);
        *(__half2*)(hsrc + i)     = __floats2half2_rn(v.x, v.y);
        *(__half2*)(hsrc + i + 2) = __floats2half2_rn(v.z, v.w);
        return;
    }
    const int tx = threadIdx.x & 31, ty = threadIdx.x >> 5;
    const int bx = bxi * 32, by = byi * 32;
    #pragma unroll
    for (int i = ty; i < 32; i += 8)
        t[i][tx] = in[(size_t)(by + i) * C + bx + tx];
    __syncthreads();
    #pragma unroll
    for (int i = ty; i < 32; i += 8)
        outp[(size_t)(bx + i) * R + by + tx] = __float2half(t[tx][i]);
}

// ---------------- fp16 tensor-core GEMM --------------------------------------
// C[M,N] = A[M,K] @ Bt[N,K]^T + bias (+optional exact GELU)
// 128x128 tile, K-tile 64, 256 thr = 8 warps (4M x 2N), warp tile 32x64,
// cp.async 2-stage pipeline, ldmatrix fragments.
#define HST 72                      // halves per smem row (144B)
#define OP_BYTES (128*HST*2)        // 18432 per operand per stage
#define GEMM_SMEM (4*OP_BYTES)      // 73728

__global__ void __launch_bounds__(256) gemm_fp16_kernel(
    const __half* __restrict__ A,
    const __half* __restrict__ B0, const __half* __restrict__ B1, const __half* __restrict__ B2,
    const float* __restrict__ bias0, const float* __restrict__ bias1, const float* __restrict__ bias2,
    float* __restrict__ C0, float* __restrict__ C1, float* __restrict__ C2,
    __half* __restrict__ H0, __half* __restrict__ H1, __half* __restrict__ H2,
    int M, int N, int K, int gelu)
{
    extern __shared__ __half sm[];
    const int z = blockIdx.z;
    const __half* Bt  = (z == 0) ? B0 : (z == 1) ? B1 : B2;
    const float* bias = (z == 0) ? bias0 : (z == 1) ? bias1 : bias2;
    float*  C = (z == 0) ? C0 : (z == 1) ? C1 : C2;
    __half* H = (z == 0) ? H0 : (z == 1) ? H1 : H2;

    const int tid = threadIdx.x, lane = tid & 31, warp = tid >> 5;
    const int wm = warp >> 1, wn = warp & 1;
    const int row0 = blockIdx.y * 128, col0 = blockIdx.x * 128;

    uint32_t smb = smem_u32(sm);
    uint32_t aB[2] = { smb,            smb + 2 * OP_BYTES };
    uint32_t bB[2] = { smb + OP_BYTES, smb + 3 * OP_BYTES };

    float acc[2][8][4];
    #pragma unroll
    for (int mt = 0; mt < 2; ++mt)
        #pragma unroll
        for (int nt = 0; nt < 8; ++nt)
            #pragma unroll
            for (int i = 0; i < 4; ++i) acc[mt][nt][i] = 0.f;

    const int aRow = wm * 32 + (lane & 15);
    const int aCol = (lane >> 4) * 8;
    const int quad = lane >> 3, ql = lane & 7;
    const int bRowB = wn * 64 + ((quad >> 1) << 3) + ql;
    const int bColB = (quad & 1) * 8;

    const int nk = K >> 6;

    #pragma unroll 1
    for (int p = 0; p < 2; ++p) {
        int k0 = p * 64;
        #pragma unroll
        for (int i = 0; i < 4; ++i) {
            int idx = tid + i * 256;
            int r = idx >> 3, ch = idx & 7;
            CP_ASYNC16(aB[p] + r * 144 + ch * 16, A  + (size_t)(row0 + r) * K + k0 + ch * 8);
            CP_ASYNC16(bB[p] + r * 144 + ch * 16, Bt + (size_t)(col0 + r) * K + k0 + ch * 8);
        }
        CP_COMMIT();
    }

    for (int s = 0; s < nk; ++s) {
        CP_WAIT1();
        __syncthreads();
        const int buf = s & 1;
        #pragma unroll
        for (int ks = 0; ks < 4; ++ks) {
            unsigned af0[4], af1[4];
            ldm_x4(af0, aB[buf] + aRow * 144 + (ks * 16 + aCol) * 2);
            ldm_x4(af1, aB[buf] + (aRow + 16) * 144 + (ks * 16 + aCol) * 2);
            #pragma unroll
            for (int pr = 0; pr < 4; ++pr) {
                unsigned bf[4];
                ldm_x4(bf, bB[buf] + (bRowB + pr * 16) * 144 + (ks * 16 + bColB) * 2);
                mma16(acc[0][2 * pr],     af0, bf[0], bf[1]);
                mma16(acc[0][2 * pr + 1], af0, bf[2], bf[3]);
                mma16(acc[1][2 * pr],     af1, bf[0], bf[1]);
                mma16(acc[1][2 * pr + 1], af1, bf[2], bf[3]);
            }
        }
        __syncthreads();
        if (s + 2 < nk) {
            int k0 = (s + 2) * 64;
            #pragma unroll
            for (int i = 0; i < 4; ++i) {
                int idx = tid + i * 256;
                int r = idx >> 3, ch = idx & 7;
                CP_ASYNC16(aB[buf] + r * 144 + ch * 16, A  + (size_t)(row0 + r) * K + k0 + ch * 8);
                CP_ASYNC16(bB[buf] + r * 144 + ch * 16, Bt + (size_t)(col0 + r) * K + k0 + ch * 8);
            }
        }
        CP_COMMIT();
    }

    const int g = lane >> 2, c4 = lane & 3;
    #pragma unroll
    for (int mt = 0; mt < 2; ++mt) {
        int r = row0 + wm * 32 + mt * 16 + g;
        #pragma unroll
        for (int nt = 0; nt < 8; ++nt) {
            int cc = col0 + wn * 64 + nt * 8 + 2 * c4;
            float bz0 = bias[cc], bz1 = bias[cc + 1];
            float v0 = acc[mt][nt][0] + bz0;
            float v1 = acc[mt][nt][1] + bz1;
            float v2 = acc[mt][nt][2] + bz0;
            float v3 = acc[mt][nt][3] + bz1;
            if (gelu) {
                v0 = 0.5f * v0 * (1.f + erff(v0 * 0.70710678118654752f));
                v1 = 0.5f * v1 * (1.f + erff(v1 * 0.70710678118654752f));
                v2 = 0.5f * v2 * (1.f + erff(v2 * 0.70710678118654752f));
                v3 = 0.5f * v3 * (1.f + erff(v3 * 0.70710678118654752f));
            }
            if (C) {
                *(float2*)(C + (size_t)r * N + cc)       = make_float2(v0, v1);
                *(float2*)(C + (size_t)(r + 8) * N + cc) = make_float2(v2, v3);
            }
            if (H) {
                *(__half2*)(H + (size_t)r * N + cc)       = __floats2half2_rn(v0, v1);
                *(__half2*)(H + (size_t)(r + 8) * N + cc) = __floats2half2_rn(v2, v3);
            }
        }
    }
}

// ---------------- fp16 flash attention (batch 0), BQ=128 ---------------------
// grid (SLEN/128, NHEAD), 256 thr = 8 warps, warp owns 16 q-rows. BK=64.
// dynamic smem layout (halves): ks0 | ks1 | vs0 | vs1 | ps(128 rows)
#define FL_KS0 0
#define FL_KS1 (64*HST)
#define FL_VS0 (2*64*HST)
#define FL_VS1 (3*64*HST)
#define FL_PS  (4*64*HST)
#define FL_SMEM ((4*64*HST + 128*HST) * 2)   // 55296 bytes

__global__ void __launch_bounds__(256) flash_fp16_kernel(
    const __half* __restrict__ Q, const __half* __restrict__ K,
    const __half* __restrict__ V, __half* __restrict__ O)
{
    extern __shared__ __half fsm[];
    const int h = blockIdx.y, q0 = blockIdx.x * 128;
    const int tid = threadIdx.x, lane = tid & 31, warp = tid >> 5;
    const int wrow = warp * 16;
    const int g = lane >> 2, c4 = lane & 3;

    uint32_t smb = smem_u32(fsm);
    uint32_t ksb[2] = { smb + FL_KS0 * 2, smb + FL_KS1 * 2 };
    uint32_t vsb[2] = { smb + FL_VS0 * 2, smb + FL_VS1 * 2 };
    uint32_t psb = smb + FL_PS * 2;
    __half* Ps = fsm + FL_PS;

    const __half* Qg = Q + (size_t)q0 * DMODEL + h * DH;
    const __half* Kg = K + h * DH;
    const __half* Vg = V + h * DH;

    // stage Q tile (128x64) into Ps, then per-warp A-frags to registers
    #pragma unroll
    for (int i = 0; i < 4; ++i) {
        int idx = tid + i * 256;
        int r = idx >> 3, ch = idx & 7;
        *(uint4*)(Ps + r * HST + ch * 8) = *(const uint4*)(Qg + (size_t)r * DMODEL + ch * 8);
    }
    __syncthreads();
    const int aRow = wrow + (lane & 15);
    const int aCol = (lane >> 4) * 8;
    unsigned qa[4][4];
    #pragma unroll
    for (int ks = 0; ks < 4; ++ks)
        ldm_x4(qa[ks], psb + aRow * 144 + (ks * 16 + aCol) * 2);

    float oacc[8][4];
    #pragma unroll
    for (int nt = 0; nt < 8; ++nt)
        #pragma unroll
        for (int i = 0; i < 4; ++i) oacc[nt][i] = 0.f;
    float m0 = -1e30f, m1 = -1e30f, l0 = 0.f, l1 = 0.f;

    const int quad = lane >> 3, ql = lane & 7;
    const int bRowS = ((quad >> 1) << 3) + ql;
    const int bColS = (quad & 1) * 8;
    const int vRow  = (quad & 1) * 8 + ql;
    const int vCol  = (quad >> 1) * 8;

    // prologue K/V loads (stages 0,1): 1024 cp.async over 256 threads
    #pragma unroll 1
    for (int p = 0; p < 2; ++p) {
        int s0 = p * 64;
        #pragma unroll
        for (int i = 0; i < 4; ++i) {
            int idx = tid + i * 256;
            if (idx < 512) {
                int r = idx >> 3, ch = idx & 7;
                CP_ASYNC16(ksb[p] + r * 144 + ch * 16, Kg + (size_t)(s0 + r) * DMODEL + ch * 8);
            } else {
                int j = idx - 512; int r = j >> 3, ch = j & 7;
                CP_ASYNC16(vsb[p] + r * 144 + ch * 16, Vg + (size_t)(s0 + r) * DMODEL + ch * 8);
            }
        }
        CP_COMMIT();
    }

    for (int kt = 0; kt < SLEN / 64; ++kt) {
        CP_WAIT1();
        __syncthreads();
        const int buf = kt & 1;

        // S = Q @ K^T
        float sacc[8][4];
        #pragma unroll
        for (int nt = 0; nt < 8; ++nt)
            #pragma unroll
            for (int i = 0; i < 4; ++i) sacc[nt][i] = 0.f;
        #pragma unroll
        for (int ks = 0; ks < 4; ++ks) {
            #pragma unroll
            for (int pr = 0; pr < 4; ++pr) {
                unsigned bf[4];
                ldm_x4(bf, ksb[buf] + (bRowS + pr * 16) * 144 + (ks * 16 + bColS) * 2);
                mma16(sacc[2 * pr],     qa[ks], bf[0], bf[1]);
                mma16(sacc[2 * pr + 1], qa[ks], bf[2], bf[3]);
            }
        }

        // online softmax (rows g and g+8 of the warp's 16)
        float mx0 = -1e30f, mx1 = -1e30f;
        #pragma unroll
        for (int nt = 0; nt < 8; ++nt) {
            mx0 = fmaxf(mx0, fmaxf(sacc[nt][0], sacc[nt][1]));
            mx1 = fmaxf(mx1, fmaxf(sacc[nt][2], sacc[nt][3]));
        }
        mx0 = fmaxf(mx0, __shfl_xor_sync(0xffffffffu, mx0, 1));
        mx0 = fmaxf(mx0, __shfl_xor_sync(0xffffffffu, mx0, 2));
        mx1 = fmaxf(mx1, __shfl_xor_sync(0xffffffffu, mx1, 1));
        mx1 = fmaxf(mx1, __shfl_xor_sync(0xffffffffu, mx1, 2));
        float m0n = fmaxf(m0, mx0 * 0.125f);
        float m1n = fmaxf(m1, mx1 * 0.125f);
        float corr0 = __expf(m0 - m0n);
        float corr1 = __expf(m1 - m1n);

        float sum0 = 0.f, sum1 = 0.f;
        #pragma unroll
        for (int nt = 0; nt < 8; ++nt) {
            float p00 = __expf(sacc[nt][0] * 0.125f - m0n);
            float p01 = __expf(sacc[nt][1] * 0.125f - m0n);
            float p10 = __expf(sacc[nt][2] * 0.125f - m1n);
            float p11 = __expf(sacc[nt][3] * 0.125f - m1n);
            sum0 += p00 + p01;
            sum1 += p10 + p11;
            *(__half2*)(Ps + (wrow + g)     * HST + nt * 8 + 2 * c4) = __floats2half2_rn(p00, p01);
            *(__half2*)(Ps + (wrow + g + 8) * HST + nt * 8 + 2 * c4) = __floats2half2_rn(p10, p11);
        }
        sum0 += __shfl_xor_sync(0xffffffffu, sum0, 1);
        sum0 += __shfl_xor_sync(0xffffffffu, sum0, 2);
        sum1 += __shfl_xor_sync(0xffffffffu, sum1, 1);
        sum1 += __shfl_xor_sync(0xffffffffu, sum1, 2);
        m0 = m0n; m1 = m1n;
        l0 = l0 * corr0 + sum0;
        l1 = l1 * corr1 + sum1;
        #pragma unroll
        for (int nt = 0; nt < 8; ++nt) {
            oacc[nt][0] *= corr0; oacc[nt][1] *= corr0;
            oacc[nt][2] *= corr1; oacc[nt][3] *= corr1;
        }
        __syncwarp();

        // O += P @ V   (P rows warp-local in Ps)
        #pragma unroll
        for (int ks = 0; ks < 4; ++ks) {
            unsigned pf[4];
            ldm_x4(pf, psb + aRow * 144 + (ks * 16 + aCol) * 2);
            #pragma unroll
            for (int pr = 0; pr < 4; ++pr) {
                unsigned bf[4];
                ldm_x4_t(bf, vsb[buf] + (vRow + ks * 16) * 144 + (vCol + pr * 16) * 2);
                mma16(oacc[2 * pr],     pf, bf[0], bf[1]);
                mma16(oacc[2 * pr + 1], pf, bf[2], bf[3]);
            }
        }
        __syncthreads();

        if (kt + 2 < SLEN / 64) {
            int s0 = (kt + 2) * 64;
            #pragma unroll
            for (int i = 0; i < 4; ++i) {
                int idx = tid + i * 256;
                if (idx < 512) {
                    int r = idx >> 3, ch = idx & 7;
                    CP_ASYNC16(ksb[buf] + r * 144 + ch * 16, Kg + (size_t)(s0 + r) * DMODEL + ch * 8);
                } else {
                    int j = idx - 512; int r = j >> 3, ch = j & 7;
                    CP_ASYNC16(vsb[buf] + r * 144 + ch * 16, Vg + (size_t)(s0 + r) * DMODEL + ch * 8);
                }
            }
        }
        CP_COMMIT();
    }

    float i0 = 1.f / l0, i1 = 1.f / l1;
    #pragma unroll
    for (int nt = 0; nt < 8; ++nt) {
        int cc = h * DH + nt * 8 + 2 * c4;
        *(__half2*)(O + (size_t)(q0 + wrow + g)     * DMODEL + cc) =
            __floats2half2_rn(oacc[nt][0] * i0, oacc[nt][1] * i0);
        *(__half2*)(O + (size_t)(q0 + wrow + g + 8) * DMODEL + cc) =
            __floats2half2_rn(oacc[nt][2] * i1, oacc[nt][3] * i1);
    }
}

// ---------------- fused residual-add + LayerNorm (+ optional half copy) ------
__global__ void __launch_bounds__(256) add_ln_kernel(
    const float* __restrict__ X, const float* __restrict__ Y,
    const float* __restrict__ g, const float* __restrict__ b,
    float* __restrict__ out, __half* __restrict__ outh, int ymod)
{
    const int row = blockIdx.x;
    const int tid = threadIdx.x;
    const float* xr = X + (size_t)row * DMODEL;
    const float* yr = Y + (size_t)(row % ymod) * DMODEL;

    float4 xv = *(const float4*)(xr + tid * 4);
    float4 yv = *(const float4*)(yr + tid * 4);
    float v0 = xv.x + yv.x, v1 = xv.y + yv.y, v2 = xv.z + yv.z, v3 = xv.w + yv.w;

    float sum = v0 + v1 + v2 + v3;
    float sq  = v0*v0 + v1*v1 + v2*v2 + v3*v3;
    #pragma unroll
    for (int off = 16; off; off >>= 1) {
        sum += __shfl_xor_sync(0xffffffffu, sum, off);
        sq  += __shfl_xor_sync(0xffffffffu, sq,  off);
    }
    __shared__ float ssum[8], ssq[8];
    int w = tid >> 5, lane = tid & 31;
    if (lane == 0) { ssum[w] = sum; ssq[w] = sq; }
    __syncthreads();
    if (tid == 0) {
        float ts = 0.f, tq = 0.f;
        #pragma unroll
        for (int i = 0; i < 8; ++i) { ts += ssum[i]; tq += ssq[i]; }
        ssum[0] = ts; ssq[0] = tq;
    }
    __syncthreads();
    const float mu   = ssum[0] * (1.f / DMODEL);
    const float var  = ssq[0] * (1.f / DMODEL) - mu * mu;
    const float rstd = rsqrtf(var + 1e-5f);

    int cc = tid * 4;
    float4 gv = *(const float4*)(g + cc);
    float4 bv = *(const float4*)(b + cc);
    float4 o;
    o.x = (v0 - mu) * rstd * gv.x + bv.x;
    o.y = (v1 - mu) * rstd * gv.y + bv.y;
    o.z = (v2 - mu) * rstd * gv.z + bv.z;
    o.w = (v3 - mu) * rstd * gv.w + bv.w;
    *(float4*)(out + (size_t)row * DMODEL + cc) = o;
    if (outh) {
        *(__half2*)(outh + (size_t)row * DMODEL + cc)     = __floats2half2_rn(o.x, o.y);
        *(__half2*)(outh + (size_t)row * DMODEL + cc + 2) = __floats2half2_rn(o.z, o.w);
    }
}

// ---------------- launch -----------------------------------------------------
extern "C" void kernel_launch(void* const* d_in, const int* in_sizes, int n_in,
                              void* d_out, int out_size)
{
    const float* src    = (const float*)d_in[0];
    const float* w_q    = (const float*)d_in[1];
    const float* b_q    = (const float*)d_in[2];
    const float* w_k    = (const float*)d_in[3];
    const float* b_k    = (const float*)d_in[4];
    const float* w_v    = (const float*)d_in[5];
    const float* b_v    = (const float*)d_in[6];
    const float* w_out  = (const float*)d_in[7];
    const float* b_out  = (const float*)d_in[8];
    const float* ln1_g  = (const float*)d_in[9];
    const float* ln1_b  = (const float*)d_in[10];
    const float* ln2_g  = (const float*)d_in[11];
    const float* ln2_b  = (const float*)d_in[12];
    const float* ffn_w1 = (const float*)d_in[13];
    const float* ffn_b1 = (const float*)d_in[14];
    const float* ffn_w2 = (const float*)d_in[15];
    const float* ffn_b2 = (const float*)d_in[16];
    float* out = (float*)d_out;

    __half *psrc, *pq, *pk, *pv, *pctx, *pxh, *pf1;
    __half *pwq, *pwk, *pwv, *pwo, *pw1, *pw2;
    float *pattn, *px, *pf2;
    cudaGetSymbolAddress((void**)&psrc, hh_src);
    cudaGetSymbolAddress((void**)&pq,   hh_q);
    cudaGetSymbolAddress((void**)&pk,   hh_k);
    cudaGetSymbolAddress((void**)&pv,   hh_v);
    cudaGetSymbolAddress((void**)&pctx, hh_ctx);
    cudaGetSymbolAddress((void**)&pxh,  hh_x);
    cudaGetSymbolAddress((void**)&pf1,  hh_f1);
    cudaGetSymbolAddress((void**)&pwq,  hh_wq);
    cudaGetSymbolAddress((void**)&pwk,  hh_wk);
    cudaGetSymbolAddress((void**)&pwv,  hh_wv);
    cudaGetSymbolAddress((void**)&pwo,  hh_wo);
    cudaGetSymbolAddress((void**)&pw1,  hh_w1);
    cudaGetSymbolAddress((void**)&pw2,  hh_w2);
    cudaGetSymbolAddress((void**)&pattn, g_attn);
    cudaGetSymbolAddress((void**)&px,    g_x);
    cudaGetSymbolAddress((void**)&pf2,   g_f2);

    cudaFuncSetAttribute(gemm_fp16_kernel,
                         cudaFuncAttributeMaxDynamicSharedMemorySize, GEMM_SMEM);
    cudaFuncSetAttribute(flash_fp16_kernel,
                         cudaFuncAttributeMaxDynamicSharedMemorySize, FL_SMEM);

    // 1) fused prep: all weight transposes + src convert
    prep_kernel<<<10240, 256>>>(src, w_q, w_k, w_v, w_out, ffn_w1, ffn_w2,
                                psrc, pwq, pwk, pwv, pwo, pw1, pw2);

    // 2) fused QKV projections (batch 0), grid.z = 3, half outputs
    gemm_fp16_kernel<<<dim3(DMODEL/128, ROWS_B0/128, 3), 256, GEMM_SMEM>>>(
        psrc, pwq, pwk, pwv, b_q, b_k, b_v,
        (float*)0, (float*)0, (float*)0, pq, pk, pv,
        ROWS_B0, DMODEL, DMODEL, 0);

    // 3) attention (batch 0), BQ=128
    flash_fp16_kernel<<<dim3(SLEN/128, NHEAD), 256, FL_SMEM>>>(pq, pk, pv, pctx);

    // 4) output projection -> f32
    gemm_fp16_kernel<<<dim3(DMODEL/128, ROWS_B0/128, 1), 256, GEMM_SMEM>>>(
        pctx, pwo, pwo, pwo, b_out, b_out, b_out,
        pattn, pattn, pattn, (__half*)0, (__half*)0, (__half*)0,
        ROWS_B0, DMODEL, DMODEL, 0);

    // 5) x = LN1(src + attn_out[0] broadcast)  -> f32 + half
    add_ln_kernel<<<ROWS_ALL, 256>>>(src, pattn, ln1_g, ln1_b, px, pxh, SLEN);

    // 6) FFN1 (+GELU) -> half
    gemm_fp16_kernel<<<dim3(DFF/128, ROWS_ALL/128, 1), 256, GEMM_SMEM>>>(
        pxh, pw1, pw1, pw1, ffn_b1, ffn_b1, ffn_b1,
        (float*)0, (float*)0, (float*)0, pf1, pf1, pf1,
        ROWS_ALL, DFF, DMODEL, 1);

    // 7) FFN2 -> f32
    gemm_fp16_kernel<<<dim3(DMODEL/128, ROWS_ALL/128, 1), 256, GEMM_SMEM>>>(
        pf1, pw2, pw2, pw2, ffn_b2, ffn_b2, ffn_b2,
        pf2, pf2, pf2, (__half*)0, (__half*)0, (__half*)0,
        ROWS_ALL, DMODEL, DFF, 0);

    // 8) out = LN2(x + ffn)
    add_ln_kernel<<<ROWS_ALL, 256>>>(px, pf2, ln2_g, ln2_b, out, (__half*)0, ROWS_ALL);
}